// round 12
// baseline (speedup 1.0000x reference)
#include <cuda_runtime.h>
#include <cuda_bf16.h>

#define GN 512
#define IMG_H 512
#define IMG_W 512
#define TILES_X 32
#define TILES_Y 32

// tanh(x) = 1 - 2/(exp(2x)+1)
__device__ __forceinline__ float fast_tanh(float x) {
    return 1.0f - __fdividef(2.0f, __expf(2.0f * x) + 1.0f);
}

// Grid (8, 32): each CTA covers a 64x16-pixel strip = 4 horizontally adjacent
// 16x16 tiles. Block 16x16 = 256 threads; each thread owns 4 consecutive
// pixels in x (one float4 store per channel).
__global__ __launch_bounds__(256) void render_wide_kernel(
    const float* __restrict__ xyz,
    const float* __restrict__ chol,
    const float* __restrict__ feat,
    const float* __restrict__ opac,
    float* __restrict__ out)
{
    const int gx  = blockIdx.x;          // strip column in [0,8)
    const int ty  = blockIdx.y;          // tile row in [0,32)
    const int tx0 = gx * 4;              // first tile column of strip
    const int lx  = threadIdx.x;         // [0,16)
    const int ly  = threadIdx.y;         // [0,16)
    const int tid = ly * 16 + lx;
    const int lane = tid & 31;

    __shared__ float4 s_p0[GN];          // cx, cy, 0.5*ca, cb
    __shared__ float4 s_p1[GN];          // 0.5*cc, f0*o, f1*o, f2*o
    __shared__ int    s_m[GN];           // 4-bit tile-column mask
    __shared__ int s_count;
    if (tid == 0) s_count = 0;
    __syncthreads();

    // Phase A: cheap cull of 2 gaussians per thread against the 4-tile strip;
    // heavy math only for survivors.
    #pragma unroll
    for (int it = 0; it < 2; it++) {
        const int i = tid + it * 256;

        float2 xy = ((const float2*)xyz)[i];
        float l0 = chol[3*i + 0] + 0.5f;
        float l1 = chol[3*i + 1];
        float l2 = chol[3*i + 2] + 0.5f;

        float cx = 256.0f * (fast_tanh(xy.x) + 1.0f);
        float cy = 256.0f * (fast_tanh(xy.y) + 1.0f);

        float cxx = l0 * l0;
        float cxy = l0 * l1;
        float cyy = l1 * l1 + l2 * l2;
        float det = cxx * cyy - cxy * cxy;

        float b  = 0.5f * (cxx + cyy);
        float v1 = fmaxf(b * b - det, 0.1f);
        v1 = b + v1 * rsqrtf(v1);                      // b + sqrt(.)
        float radius = ceilf(3.0f * v1 * rsqrtf(v1));  // ceil(3*sqrt(v1))

        int tminx = (int)((cx - radius) * 0.0625f);
        int tmaxx = (int)((cx + radius) * 0.0625f) + 1;
        int tminy = (int)((cy - radius) * 0.0625f);
        int tmaxy = (int)((cy + radius) * 0.0625f) + 1;

        bool iny  = (ty >= tminy) && (ty < tmaxy);
        bool pred = iny && (tminx <= tx0 + 3) && (tmaxx > tx0);

        unsigned m = __ballot_sync(0xffffffffu, pred);
        if (m) {
            int base = 0;
            if (lane == 0) base = atomicAdd(&s_count, __popc(m));
            base = __shfl_sync(0xffffffffu, base, 0);
            if (pred) {
                int cm = 0;
                #pragma unroll
                for (int c = 0; c < 4; c++)
                    if (tminx <= tx0 + c && tmaxx > tx0 + c) cm |= (1 << c);
                float inv_det = __fdividef(1.0f, det);
                float o = opac[i];
                int p = base + __popc(m & ((1u << lane) - 1u));
                s_p0[p] = make_float4(cx, cy, 0.5f * cyy * inv_det, -cxy * inv_det);
                s_p1[p] = make_float4(0.5f * cxx * inv_det,
                                      feat[3*i + 0] * o,
                                      feat[3*i + 1] * o,
                                      feat[3*i + 2] * o);
                s_m[p] = cm;
            }
        }
    }
    __syncthreads();
    const int cnt = s_count;

    // Phase B: 4 consecutive pixels per thread (same row).
    const int   x0  = gx * 64 + lx * 4;      // first pixel x
    const float px0 = (float)x0;
    const float py  = (float)(ty * 16 + ly);
    const int   qc  = lx >> 2;               // tile column within strip [0,4)

    float a0[4] = {0,0,0,0}, a1[4] = {0,0,0,0}, a2[4] = {0,0,0,0};

    for (int k = 0; k < cnt; k++) {
        float4 p0 = s_p0[k];                 // broadcast LDS
        float4 p1 = s_p1[k];
        float bit = (float)((s_m[k] >> qc) & 1);

        float dy     = p0.y - py;
        float dyterm = p1.x * dy * dy;       // 0.5*cc*dy^2 shared by 4 px
        float bdy    = p0.w * dy;            // cb*dy

        #pragma unroll
        for (int j = 0; j < 4; j++) {
            float dx = p0.x - (px0 + (float)j);
            float sigma = p0.z * dx * dx + dyterm + bdy * dx;
            float w = bit * __expf(-sigma);
            a0[j] += w * p1.y;
            a1[j] += w * p1.z;
            a2[j] += w * p1.w;
        }
    }

    float4 o0, o1, o2;
    o0.x = fminf(fmaxf(a0[0],0.f),1.f); o0.y = fminf(fmaxf(a0[1],0.f),1.f);
    o0.z = fminf(fmaxf(a0[2],0.f),1.f); o0.w = fminf(fmaxf(a0[3],0.f),1.f);
    o1.x = fminf(fmaxf(a1[0],0.f),1.f); o1.y = fminf(fmaxf(a1[1],0.f),1.f);
    o1.z = fminf(fmaxf(a1[2],0.f),1.f); o1.w = fminf(fmaxf(a1[3],0.f),1.f);
    o2.x = fminf(fmaxf(a2[0],0.f),1.f); o2.y = fminf(fmaxf(a2[1],0.f),1.f);
    o2.z = fminf(fmaxf(a2[2],0.f),1.f); o2.w = fminf(fmaxf(a2[3],0.f),1.f);

    const int row = ty * 16 + ly;
    float4* outv = (float4*)(out + row * IMG_W + x0);
    outv[0]                         = o0;   // channel 0 plane
    outv[IMG_H * IMG_W / 4 * 1]     = o1;   // channel 1 plane (offset in float4s)
    outv[IMG_H * IMG_W / 4 * 2]     = o2;   // channel 2 plane
}

extern "C" void kernel_launch(void* const* d_in, const int* in_sizes, int n_in,
                              void* d_out, int out_size)
{
    const float* xyz  = (const float*)d_in[0];
    const float* chol = (const float*)d_in[1];
    const float* feat = (const float*)d_in[2];
    const float* opac = (const float*)d_in[3];
    float* out = (float*)d_out;

    dim3 grid(8, 32);
    dim3 block(16, 16);
    render_wide_kernel<<<grid, block>>>(xyz, chol, feat, opac, out);
}

// round 13
// speedup vs baseline: 1.0250x; 1.0250x over previous
#include <cuda_runtime.h>
#include <cuda_bf16.h>

#define GN 512
#define IMG_H 512
#define IMG_W 512
#define BLOCK_H 16
#define BLOCK_W 16
#define TILES_X 32
#define TILES_Y 32

// tanh(x) = 1 - 2/(exp(2x)+1)
__device__ __forceinline__ float fast_tanh(float x) {
    return 1.0f - __fdividef(2.0f, __expf(2.0f * x) + 1.0f);
}

// Grid 32x32 tiles, block 16x16. Per-warp segmented compaction:
// warp w owns gaussians [w*64, (w+1)*64) and shared segment [w*64, ...).
// No shared atomics, single __syncthreads per CTA.
__global__ __launch_bounds__(256) void render_fused_kernel(
    const float* __restrict__ xyz,
    const float* __restrict__ chol,
    const float* __restrict__ feat,
    const float* __restrict__ opac,
    float* __restrict__ out)
{
    const int tx = blockIdx.x;   // tile x
    const int ty = blockIdx.y;   // tile y
    const int lx = threadIdx.x;
    const int ly = threadIdx.y;
    const int tid = ly * BLOCK_W + lx;
    const int wid = tid >> 5;    // warp id [0,8)
    const int lane = tid & 31;

    __shared__ float4 s_p0[GN];  // cx, cy, 0.5*ca, cb
    __shared__ float4 s_p1[GN];  // 0.5*cc, f0*o, f1*o, f2*o
    __shared__ int    s_cnt[8];  // survivors per warp segment

    const int seg = wid * 64;    // this warp's gaussian range & shared segment
    int off = 0;                 // running count within segment (register)

    // Phase A: warp-local cull + compaction. No CTA-wide coordination needed.
    #pragma unroll
    for (int it = 0; it < 2; it++) {
        const int i = seg + it * 32 + lane;

        float2 xy = ((const float2*)xyz)[i];
        float l0 = chol[3*i + 0] + 0.5f;
        float l1 = chol[3*i + 1];
        float l2 = chol[3*i + 2] + 0.5f;

        float cx = 256.0f * (fast_tanh(xy.x) + 1.0f);
        float cy = 256.0f * (fast_tanh(xy.y) + 1.0f);

        float cxx = l0 * l0;
        float cxy = l0 * l1;
        float cyy = l1 * l1 + l2 * l2;
        float det = cxx * cyy - cxy * cxy;

        float b  = 0.5f * (cxx + cyy);
        float v1 = fmaxf(b * b - det, 0.1f);
        v1 = b + v1 * rsqrtf(v1);                      // b + sqrt(.)
        float radius = ceilf(3.0f * v1 * rsqrtf(v1));  // ceil(3*sqrt(v1))

        // Unclamped bounds equivalent to clamped for tx,ty in [0,32)
        int tminx = (int)((cx - radius) * (1.0f / BLOCK_W));
        int tmaxx = (int)((cx + radius) * (1.0f / BLOCK_W)) + 1;
        int tminy = (int)((cy - radius) * (1.0f / BLOCK_H));
        int tmaxy = (int)((cy + radius) * (1.0f / BLOCK_H)) + 1;

        bool pred = (tx >= tminx) && (tx < tmaxx) && (ty >= tminy) && (ty < tmaxy);

        unsigned m = __ballot_sync(0xffffffffu, pred);
        if (pred) {
            // Rare path: ~2 threads per CTA reach here.
            float inv_det = __fdividef(1.0f, det);
            float o = opac[i];
            int p = seg + off + __popc(m & ((1u << lane) - 1u));
            s_p0[p] = make_float4(cx, cy, 0.5f * cyy * inv_det, -cxy * inv_det);
            s_p1[p] = make_float4(0.5f * cxx * inv_det,
                                  feat[3*i + 0] * o,
                                  feat[3*i + 1] * o,
                                  feat[3*i + 2] * o);
        }
        off += __popc(m);
    }
    if (lane == 0) s_cnt[wid] = off;
    __syncthreads();   // the only CTA-wide barrier

    // Prefetch all 8 segment counts with two LDS.128
    int4 c03 = ((const int4*)s_cnt)[0];
    int4 c47 = ((const int4*)s_cnt)[1];
    int cnts[8] = {c03.x, c03.y, c03.z, c03.w, c47.x, c47.y, c47.z, c47.w};

    // Phase B: accumulate survivors (8 segments) for this thread's pixel.
    const float px = (float)(tx * BLOCK_W + lx);
    const float py = (float)(ty * BLOCK_H + ly);

    float acc0 = 0.0f, acc1 = 0.0f, acc2 = 0.0f;
    #pragma unroll
    for (int w = 0; w < 8; w++) {
        const int cw = cnts[w];
        for (int k = 0; k < cw; k++) {
            float4 p0 = s_p0[w * 64 + k];   // broadcast LDS
            float4 p1 = s_p1[w * 64 + k];
            float dx = p0.x - px;
            float dy = p0.y - py;
            float sigma = p0.z * dx * dx + p1.x * dy * dy + p0.w * dx * dy;
            float w0 = __expf(-sigma);
            acc0 += w0 * p1.y;
            acc1 += w0 * p1.z;
            acc2 += w0 * p1.w;
        }
    }

    acc0 = fminf(fmaxf(acc0, 0.0f), 1.0f);
    acc1 = fminf(fmaxf(acc1, 0.0f), 1.0f);
    acc2 = fminf(fmaxf(acc2, 0.0f), 1.0f);

    const int pix = (ty * BLOCK_H + ly) * IMG_W + (tx * BLOCK_W + lx);
    out[0 * IMG_H * IMG_W + pix] = acc0;
    out[1 * IMG_H * IMG_W + pix] = acc1;
    out[2 * IMG_H * IMG_W + pix] = acc2;
}

extern "C" void kernel_launch(void* const* d_in, const int* in_sizes, int n_in,
                              void* d_out, int out_size)
{
    const float* xyz  = (const float*)d_in[0];
    const float* chol = (const float*)d_in[1];
    const float* feat = (const float*)d_in[2];
    const float* opac = (const float*)d_in[3];
    float* out = (float*)d_out;

    dim3 grid(TILES_X, TILES_Y);
    dim3 block(BLOCK_W, BLOCK_H);
    render_fused_kernel<<<grid, block>>>(xyz, chol, feat, opac, out);
}

// round 14
// speedup vs baseline: 1.0551x; 1.0294x over previous
#include <cuda_runtime.h>
#include <cuda_bf16.h>

// Problem constants (match reference)
#define GN 512
#define IMG_H 512
#define IMG_W 512
#define BLOCK_H 16
#define BLOCK_W 16
#define TILES_X 32
#define TILES_Y 32

// tanh(x) = 1 - 2/(exp(2x)+1); __expf+__fdividef => ~4 instr, ~1e-7 abs err
__device__ __forceinline__ float fast_tanh(float x) {
    return 1.0f - __fdividef(2.0f, __expf(2.0f * x) + 1.0f);
}

// CONVERGED KERNEL (R3 structure; 15-round study).
// Fused single-launch 2D gaussian splatting: grid = 32x32 tiles,
// block = 16x16 pixels.
//  Phase A: 256 threads cull 512 gaussians (2 each) with a cheap
//           center/radius test; only survivors (~2/CTA) run the division +
//           feature loads, compacting params to shared via warp-aggregated
//           atomics.
//  Phase B: each thread accumulates its pixel over survivors from broadcast
//           shared-memory reads.
// Measured floor: ~4.5us launch/ramp + ~1.5-2us issue work + ~2.2us graph
// replay gap. All 14 structural variants (work scaling, CTA sizing, PDL,
// chain shortening, wide stores, segmented compaction) land within noise of
// this configuration; this source holds the best observed total (8.70us).
__global__ __launch_bounds__(256) void render_fused_kernel(
    const float* __restrict__ xyz,
    const float* __restrict__ chol,
    const float* __restrict__ feat,
    const float* __restrict__ opac,
    float* __restrict__ out)
{
    const int tx = blockIdx.x;   // tile x
    const int ty = blockIdx.y;   // tile y
    const int lx = threadIdx.x;
    const int ly = threadIdx.y;
    const int tid = ly * BLOCK_W + lx;
    const int lane = tid & 31;

    __shared__ float4 s_p0[GN];  // cx, cy, 0.5*ca, cb
    __shared__ float4 s_p1[GN];  // 0.5*cc, f0*o, f1*o, f2*o
    __shared__ int s_count;
    if (tid == 0) s_count = 0;
    __syncthreads();

    // Phase A: cheap cull; full params only for survivors.
    #pragma unroll
    for (int it = 0; it < 2; it++) {
        const int i = tid + it * 256;

        float2 xy = ((const float2*)xyz)[i];
        float l0 = chol[3*i + 0] + 0.5f;
        float l1 = chol[3*i + 1];
        float l2 = chol[3*i + 2] + 0.5f;

        float mx = fast_tanh(xy.x);
        float my = fast_tanh(xy.y);
        float cx = 0.5f * (float)IMG_W * (mx + 1.0f);
        float cy = 0.5f * (float)IMG_H * (my + 1.0f);

        float cxx = l0 * l0;
        float cxy = l0 * l1;
        float cyy = l1 * l1 + l2 * l2;
        float det = cxx * cyy - cxy * cxy;

        float b  = 0.5f * (cxx + cyy);
        float v1 = fmaxf(b * b - det, 0.1f);
        v1 = b + v1 * rsqrtf(v1);                      // b + sqrt(v1)
        float radius = ceilf(3.0f * v1 * rsqrtf(v1));  // ceil(3*sqrt(v1))

        // Unclamped bounds are equivalent to clamped ones for tx,ty in [0,32)
        int tminx = (int)((cx - radius) * (1.0f / BLOCK_W));
        int tmaxx = (int)((cx + radius) * (1.0f / BLOCK_W)) + 1;
        int tminy = (int)((cy - radius) * (1.0f / BLOCK_H));
        int tmaxy = (int)((cy + radius) * (1.0f / BLOCK_H)) + 1;

        bool pred = (tx >= tminx) && (tx < tmaxx) && (ty >= tminy) && (ty < tmaxy);

        // Warp-aggregated compaction
        unsigned m = __ballot_sync(0xffffffffu, pred);
        if (m) {
            int base = 0;
            if (lane == 0) base = atomicAdd(&s_count, __popc(m));
            base = __shfl_sync(0xffffffffu, base, 0);
            if (pred) {
                // Expensive path: only ~2 threads per CTA reach here.
                float inv_det = __fdividef(1.0f, det);
                float ca = cyy * inv_det;
                float cb = -cxy * inv_det;
                float cc = cxx * inv_det;
                float o = opac[i];
                int p = base + __popc(m & ((1u << lane) - 1u));
                s_p0[p] = make_float4(cx, cy, 0.5f * ca, cb);
                s_p1[p] = make_float4(0.5f * cc,
                                      feat[3*i + 0] * o,
                                      feat[3*i + 1] * o,
                                      feat[3*i + 2] * o);
            }
        }
    }
    __syncthreads();
    const int cnt = s_count;

    // Phase B: accumulate survivors for this thread's pixel.
    const float px = (float)(tx * BLOCK_W + lx);
    const float py = (float)(ty * BLOCK_H + ly);

    float acc0 = 0.0f, acc1 = 0.0f, acc2 = 0.0f;
    for (int k = 0; k < cnt; k++) {
        float4 p0 = s_p0[k];   // broadcast LDS
        float4 p1 = s_p1[k];
        float dx = p0.x - px;
        float dy = p0.y - py;
        float sigma = p0.z * dx * dx + p1.x * dy * dy + p0.w * dx * dy;
        float w = __expf(-sigma);
        acc0 += w * p1.y;
        acc1 += w * p1.z;
        acc2 += w * p1.w;
    }

    acc0 = fminf(fmaxf(acc0, 0.0f), 1.0f);
    acc1 = fminf(fmaxf(acc1, 0.0f), 1.0f);
    acc2 = fminf(fmaxf(acc2, 0.0f), 1.0f);

    const int pix = (ty * BLOCK_H + ly) * IMG_W + (tx * BLOCK_W + lx);
    out[0 * IMG_H * IMG_W + pix] = acc0;
    out[1 * IMG_H * IMG_W + pix] = acc1;
    out[2 * IMG_H * IMG_W + pix] = acc2;
}

extern "C" void kernel_launch(void* const* d_in, const int* in_sizes, int n_in,
                              void* d_out, int out_size)
{
    const float* xyz  = (const float*)d_in[0];
    const float* chol = (const float*)d_in[1];
    const float* feat = (const float*)d_in[2];
    const float* opac = (const float*)d_in[3];
    float* out = (float*)d_out;

    dim3 grid(TILES_X, TILES_Y);
    dim3 block(BLOCK_W, BLOCK_H);
    render_fused_kernel<<<grid, block>>>(xyz, chol, feat, opac, out);
}